// round 14
// baseline (speedup 1.0000x reference)
#include <cuda_runtime.h>

// ===================== Problem constants =====================
// M=3, N=8, G=8, K=3
// x: (32, 3, 224, 224) f32   w: (24, 1, 3, 3) f32
// out: (32, 192, 222, 222) f32, grouped conv: out channel o uses in channel o/64

#define IMG 224
#define OUT 222
#define NCH 192
#define PLANE_OUT (OUT*OUT)        // 49284

typedef unsigned long long u64;

// duplicated rotated weights (w,w) as u64, padded layout [192][10]:
// g_rotw2[o*10 + j], j<9 real (dy*3+dx), j==9 zero pad -> 80B stride, 16B aligned
__device__ u64 g_rotw2[192 * 10];

__device__ __forceinline__ u64 ffma2(u64 a, u64 b, u64 c) {
    u64 d;
    asm("fma.rn.f32x2 %0, %1, %2, %3;" : "=l"(d) : "l"(a), "l"(b), "l"(c));
    return d;
}
__device__ __forceinline__ u64 pack2(float lo, float hi) {
    u64 d;
    asm("mov.b64 %0, {%1, %2};" : "=l"(d) : "f"(lo), "f"(hi));
    return d;
}
__device__ __forceinline__ void unpack2(u64 v, float& lo, float& hi) {
    asm("mov.b64 {%0, %1}, %2;" : "=f"(lo), "=f"(hi) : "l"(v));
}
// streaming store: output is write-once, never re-read -> evict-first in L2
__device__ __forceinline__ void st_cs64(float* p, u64 v) {
    asm volatile("st.global.cs.b64 [%0], %1;" :: "l"(p), "l"(v) : "memory");
}

// ===================== Kernel 1: rotate weights =====================
__global__ void rotw_kernel(const float* __restrict__ w) {
    int t = blockIdx.x * blockDim.x + threadIdx.x;
    if (t >= 192 * 10) return;
    int o = t / 10, j = t % 10;
    if (j == 9) { g_rotw2[t] = 0ull; return; }   // pad slot
    int mn = o >> 3, g = o & 7;
    int hh = j / 3, ww = j % 3;

    // angle: linspace(-90, 90, 8)[g] degrees -> radians (double, like numpy)
    double ang = (-90.0 + (180.0 / 7.0) * (double)g) * 0.017453292519943295;
    float c = (float)cos(ang);
    float s = (float)sin(ang);

    float cx = (2.0f * ww + 1.0f) / 3.0f - 1.0f;
    float cy = (2.0f * hh + 1.0f) / 3.0f - 1.0f;
    float gx = c * cx - s * cy;
    float gy = s * cx + c * cy;

    float ix = ((gx + 1.0f) * 3.0f - 1.0f) * 0.5f;
    float iy = ((gy + 1.0f) * 3.0f - 1.0f) * 0.5f;
    float x0f = floorf(ix), y0f = floorf(iy);
    int   x0  = (int)x0f,   y0  = (int)y0f;
    float wx1 = ix - x0f, wy1 = iy - y0f;
    float wx0 = 1.0f - wx1, wy0 = 1.0f - wy1;

    const float* wp = w + mn * 9;
    float v00 = 0.f, v10 = 0.f, v01 = 0.f, v11 = 0.f;
    int x1 = x0 + 1, y1 = y0 + 1;
    bool bx0 = (x0 >= 0 && x0 < 3), bx1 = (x1 >= 0 && x1 < 3);
    bool by0 = (y0 >= 0 && y0 < 3), by1 = (y1 >= 0 && y1 < 3);
    if (bx0 && by0) v00 = wp[y0 * 3 + x0];
    if (bx1 && by0) v10 = wp[y0 * 3 + x1];
    if (bx0 && by1) v01 = wp[y1 * 3 + x0];
    if (bx1 && by1) v11 = wp[y1 * 3 + x1];

    float v = v00 * (wx0 * wy0) + v10 * (wx1 * wy0)
            + v01 * (wx0 * wy1) + v11 * (wx1 * wy1);

    g_rotw2[t] = pack2(v, v);
}

// ===================== Kernel 2: grouped conv, FULL-WIDTH 222x6 tiles =====================
// R11 champion geometry (234us): CTA 224 threads = 112 x-threads x 2 y-threads,
// thread = 1 col-pair x 3 rows, all 64 channels, wv[9] weights (80B stride,
// 4x LDS.128 + 1x LDS.64), .cs streaming STG.64 (warp = contiguous 256B).
// 5 CTAs/SM (regs ~58) is the measured optimum (4 and 6 both slower).
// ONLY change vs R11: input tile + weight smem fill vectorized to 128-bit
// (1792 floats = 448 float4 = exactly 2 LDG.128/STS.128 per thread).
#define TH 6
#define IN_H 8     // 6 + 2 halo rows

__global__ void __launch_bounds__(224)
conv_kernel(const float* __restrict__ x, float* __restrict__ out) {
    __shared__ __align__(16) float s_in[IN_H * IMG];   // 7168 B
    __shared__ __align__(16) u64   s_w[64 * 10];       // 5120 B

    int nm  = blockIdx.z;          // n*3 + m
    int m   = nm % 3;
    int ty0 = blockIdx.y * TH;     // first output row of tile (0..216)
    int tid = threadIdx.x;

    // vectorized input tile load: rows ty0..ty0+7 all exist (ty0 <= 216).
    // base = xp + ty0*IMG: byte offset (nm*50176 + ty0*224)*4 ≡ 0 mod 16.
    {
        const float4* src = (const float4*)(x + (size_t)nm * (IMG * IMG) + (size_t)ty0 * IMG);
        float4* dst = (float4*)s_in;
#pragma unroll
        for (int i = 0; i < 2; i++) {
            int idx = tid + i * 224;             // 448 float4s total
            dst[idx] = src[idx];
        }
    }
    // weights for this group (padded duplicated-pair layout, 80B/channel)
    {
        const ulonglong2* gw = (const ulonglong2*)(g_rotw2 + (size_t)m * 64 * 10);
        ulonglong2* dw = (ulonglong2*)s_w;
        for (int i = tid; i < 64 * 10 / 2; i += 224) dw[i] = gw[i];   // 320 x 16B
    }
    __syncthreads();

    int xi = tid % 112;            // col-pair index
    int yi = tid / 112;            // 0..1
    if (xi >= 111) return;         // pair 111 = cols 222-223 (invalid); no syncs follow
    int ox = 2 * xi;
    int ly = 3 * yi;               // 0 or 3
    int oy = ty0 + ly;             // rows oy..oy+2 always valid (oy <= 219)

    // register-resident input pairs: rows ly..ly+4, 3 overlapping pairs each
    u64 ip[5][3];
#pragma unroll
    for (int r = 0; r < 5; r++) {
        const u64* p = (const u64*)&s_in[(ly + r) * IMG + ox];   // 8B aligned
        u64 a = p[0], b = p[1];
        float a0, a1, a2, a3;
        unpack2(a, a0, a1);
        unpack2(b, a2, a3);
        ip[r][0] = a;
        ip[r][1] = pack2(a1, a2);
        ip[r][2] = b;
    }

    int n = nm / 3;
    float* outp = out + (size_t)(n * NCH + m * 64) * PLANE_OUT
                      + (size_t)oy * OUT + ox;

    for (int c = 0; c < 64; c++) {
        // 5 vector LDS: 80B stride keeps rows 16B aligned
        const u64* wc = &s_w[c * 10];
        ulonglong2 wA = *(const ulonglong2*)(wc + 0);   // w0 w1
        ulonglong2 wB = *(const ulonglong2*)(wc + 2);   // w2 w3
        ulonglong2 wC = *(const ulonglong2*)(wc + 4);   // w4 w5
        ulonglong2 wD = *(const ulonglong2*)(wc + 6);   // w6 w7
        u64 w8 = wc[8];
        u64 wv[9] = { wA.x, wA.y, wB.x, wB.y, wC.x, wC.y, wD.x, wD.y, w8 };

        u64 acc0 = 0, acc1 = 0, acc2 = 0;
#pragma unroll
        for (int dy = 0; dy < 3; dy++) {
#pragma unroll
            for (int dx = 0; dx < 3; dx++) {
                u64 wt = wv[dy * 3 + dx];
                acc0 = ffma2(ip[0 + dy][dx], wt, acc0);
                acc1 = ffma2(ip[1 + dy][dx], wt, acc1);
                acc2 = ffma2(ip[2 + dy][dx], wt, acc2);
            }
        }
        st_cs64(outp,           acc0);
        st_cs64(outp + OUT,     acc1);
        st_cs64(outp + 2 * OUT, acc2);
        outp += PLANE_OUT;
    }
}

// ===================== launch =====================
extern "C" void kernel_launch(void* const* d_in, const int* in_sizes, int n_in,
                              void* d_out, int out_size) {
    const float* x = (const float*)d_in[0];
    const float* w = (const float*)d_in[1];
    float* out = (float*)d_out;

    rotw_kernel<<<8, 256>>>(w);    // 192*10 = 1920 slots

    dim3 grid(1,
              37,                  // 222/6 exact full-width row tiles
              32 * 3);             // 96 (n,m) planes
    conv_kernel<<<grid, 224>>>(x, out);
}

// round 17
// speedup vs baseline: 1.0512x; 1.0512x over previous
#include <cuda_runtime.h>

// ===================== Problem constants =====================
// M=3, N=8, G=8, K=3
// x: (32, 3, 224, 224) f32   w: (24, 1, 3, 3) f32
// out: (32, 192, 222, 222) f32, grouped conv: out channel o uses in channel o/64

#define IMG 224
#define OUT 222
#define NCH 192
#define PLANE_OUT (OUT*OUT)        // 49284

typedef unsigned long long u64;

// (cos, sin) of linspace(-90, 90, 8) degrees, double-evaluated then float-rounded
// (bit-identical to (float)cos((double)radians(ang)) used previously).
__constant__ float2 c_cs[8] = {
    {6.123233995736766e-17f, -1.0f},
    {0.4338837391175581f,  -0.9009688679024191f},
    {0.7818314824680298f,  -0.6234898018587336f},
    {0.9749279121818236f,  -0.2225209339563144f},
    {0.9749279121818236f,   0.2225209339563144f},
    {0.7818314824680298f,   0.6234898018587336f},
    {0.4338837391175581f,   0.9009688679024191f},
    {6.123233995736766e-17f, 1.0f},
};

__device__ __forceinline__ u64 ffma2(u64 a, u64 b, u64 c) {
    u64 d;
    asm("fma.rn.f32x2 %0, %1, %2, %3;" : "=l"(d) : "l"(a), "l"(b), "l"(c));
    return d;
}
__device__ __forceinline__ u64 pack2(float lo, float hi) {
    u64 d;
    asm("mov.b64 %0, {%1, %2};" : "=l"(d) : "f"(lo), "f"(hi));
    return d;
}
__device__ __forceinline__ void unpack2(u64 v, float& lo, float& hi) {
    asm("mov.b64 {%0, %1}, %2;" : "=f"(lo), "=f"(hi) : "l"(v));
}
// streaming store: output is write-once, never re-read -> evict-first in L2
__device__ __forceinline__ void st_cs64(float* p, u64 v) {
    asm volatile("st.global.cs.b64 [%0], %1;" :: "l"(p), "l"(v) : "memory");
}

// ===================== grouped conv, FULL-WIDTH 222x6 tiles =====================
// R11 champion geometry (proven 234us): CTA 224 threads = 112 x-threads x 2
// y-threads, thread = 1 col-pair x 3 rows, all 64 channels of group m,
// wv[9] weights (80B padded stride: 4x LDS.128 + 1x LDS.64 per channel),
// .cs streaming STG.64 (warp = 32 consecutive col-pairs = contiguous 256B).
// 5 CTAs/SM (regs ~58) is the measured optimum. Scalar interleaved tile load
// (vectorized prologue measurably regresses via cross-CTA L1tex contention).
// ONLY change vs R11: weight rotation computed inline per CTA (hardcoded trig
// table) -> no separate rotw kernel, no g_rotw2 global round-trip.
#define TH 6
#define IN_H 8     // 6 + 2 halo rows

__global__ void __launch_bounds__(224)
conv_kernel(const float* __restrict__ x, const float* __restrict__ w,
            float* __restrict__ out) {
    __shared__ __align__(16) float s_in[IN_H * IMG];   // 7168 B
    __shared__ __align__(16) u64   s_w[64 * 10];       // 5120 B

    int nm  = blockIdx.z;          // n*3 + m
    int m   = nm % 3;
    int ty0 = blockIdx.y * TH;     // first output row of tile (0..216)
    int tid = threadIdx.x;

    const float* xp = x + (size_t)nm * (IMG * IMG);

    // cooperative input load: 224 threads = exactly one full 896B row per pass.
    // Rows ty0..ty0+7 all exist (ty0 <= 216) -> no clamp. Scalar on purpose.
    for (int i = tid; i < IN_H * IMG; i += 224) {
        int r  = i / IMG, cc = i % IMG;
        s_in[i] = xp[(ty0 + r) * IMG + cc];
    }

    // Inline weight rotation for this group's 64 channels -> s_w[64][10]
    // (j<9 real taps as duplicated (v,v) pairs, j==9 zero pad for 80B stride).
    for (int i = tid; i < 64 * 10; i += 224) {
        int cc = i / 10, j = i % 10;
        if (j == 9) { s_w[i] = 0ull; continue; }
        int o  = m * 64 + cc;          // global output channel
        int mn = o >> 3, g = o & 7;
        int hh = j / 3, ww = j % 3;

        float c = c_cs[g].x, s = c_cs[g].y;

        float cx = (2.0f * ww + 1.0f) / 3.0f - 1.0f;
        float cy = (2.0f * hh + 1.0f) / 3.0f - 1.0f;
        float gx = c * cx - s * cy;
        float gy = s * cx + c * cy;

        float ix = ((gx + 1.0f) * 3.0f - 1.0f) * 0.5f;
        float iy = ((gy + 1.0f) * 3.0f - 1.0f) * 0.5f;
        float x0f = floorf(ix), y0f = floorf(iy);
        int   x0  = (int)x0f,   y0  = (int)y0f;
        float wx1 = ix - x0f, wy1 = iy - y0f;
        float wx0 = 1.0f - wx1, wy0 = 1.0f - wy1;

        const float* wp = w + mn * 9;      // w is (24,1,3,3); hot in L1/L2
        float v00 = 0.f, v10 = 0.f, v01 = 0.f, v11 = 0.f;
        int x1 = x0 + 1, y1 = y0 + 1;
        bool bx0 = (x0 >= 0 && x0 < 3), bx1 = (x1 >= 0 && x1 < 3);
        bool by0 = (y0 >= 0 && y0 < 3), by1 = (y1 >= 0 && y1 < 3);
        if (bx0 && by0) v00 = wp[y0 * 3 + x0];
        if (bx1 && by0) v10 = wp[y0 * 3 + x1];
        if (bx0 && by1) v01 = wp[y1 * 3 + x0];
        if (bx1 && by1) v11 = wp[y1 * 3 + x1];

        float v = v00 * (wx0 * wy0) + v10 * (wx1 * wy0)
                + v01 * (wx0 * wy1) + v11 * (wx1 * wy1);

        s_w[i] = pack2(v, v);
    }
    __syncthreads();

    int xi = tid % 112;            // col-pair index
    int yi = tid / 112;            // 0..1
    if (xi >= 111) return;         // pair 111 = cols 222-223 (invalid); no syncs follow
    int ox = 2 * xi;
    int ly = 3 * yi;               // 0 or 3
    int oy = ty0 + ly;             // rows oy..oy+2 always valid (oy <= 219)

    // register-resident input pairs: rows ly..ly+4, 3 overlapping pairs each
    u64 ip[5][3];
#pragma unroll
    for (int r = 0; r < 5; r++) {
        const u64* p = (const u64*)&s_in[(ly + r) * IMG + ox];   // 8B aligned
        u64 a = p[0], b = p[1];
        float a0, a1, a2, a3;
        unpack2(a, a0, a1);
        unpack2(b, a2, a3);
        ip[r][0] = a;
        ip[r][1] = pack2(a1, a2);
        ip[r][2] = b;
    }

    int n = nm / 3;
    float* outp = out + (size_t)(n * NCH + m * 64) * PLANE_OUT
                      + (size_t)oy * OUT + ox;

    for (int c = 0; c < 64; c++) {
        // 5 vector LDS: 80B stride keeps rows 16B aligned
        const u64* wc = &s_w[c * 10];
        ulonglong2 wA = *(const ulonglong2*)(wc + 0);   // w0 w1
        ulonglong2 wB = *(const ulonglong2*)(wc + 2);   // w2 w3
        ulonglong2 wC = *(const ulonglong2*)(wc + 4);   // w4 w5
        ulonglong2 wD = *(const ulonglong2*)(wc + 6);   // w6 w7
        u64 w8 = wc[8];
        u64 wv[9] = { wA.x, wA.y, wB.x, wB.y, wC.x, wC.y, wD.x, wD.y, w8 };

        u64 acc0 = 0, acc1 = 0, acc2 = 0;
#pragma unroll
        for (int dy = 0; dy < 3; dy++) {
#pragma unroll
            for (int dx = 0; dx < 3; dx++) {
                u64 wt = wv[dy * 3 + dx];
                acc0 = ffma2(ip[0 + dy][dx], wt, acc0);
                acc1 = ffma2(ip[1 + dy][dx], wt, acc1);
                acc2 = ffma2(ip[2 + dy][dx], wt, acc2);
            }
        }
        st_cs64(outp,           acc0);
        st_cs64(outp + OUT,     acc1);
        st_cs64(outp + 2 * OUT, acc2);
        outp += PLANE_OUT;
    }
}

// ===================== launch =====================
extern "C" void kernel_launch(void* const* d_in, const int* in_sizes, int n_in,
                              void* d_out, int out_size) {
    const float* x = (const float*)d_in[0];
    const float* w = (const float*)d_in[1];
    float* out = (float*)d_out;

    dim3 grid(1,
              37,                  // 222/6 exact full-width row tiles
              32 * 3);             // 96 (n,m) planes
    conv_kernel<<<grid, 224>>>(x, w, out);
}